// round 10
// baseline (speedup 1.0000x reference)
#include <cuda_runtime.h>
#include <cuda_fp16.h>
#include <math.h>

// Problem constants (match reference)
#define NN 50000
#define NE 800000
#define IN_F 256
#define D1 128      // HEADS*HID
#define OUT_F 64
#define SLOPE 0.2f

#define SCAN_B 1024
#define NBLK ((NN + SCAN_B - 1) / SCAN_B)   // 49

// ---------------- device scratch (no allocations allowed) ----------------
__device__ __align__(16) float g_h[(size_t)NN * D1];     // GEMM output (fp32)
__device__ __align__(16) float g_act[(size_t)NN * D1];   // post-aggregate activations
__device__ __align__(16) float g_als[(size_t)NN * 4];
__device__ __align__(16) float g_ald[(size_t)NN * 4];
__device__ int   g_rowptr[NN + 1];
__device__ int   g_deg[NN];
__device__ int   g_cursor[NN];
__device__ __align__(8) int2 g_csr[NE];    // (src, weight-bits) packed
__device__ int   g_bsum[NBLK];
__device__ int   g_boff[NBLK];
__device__ unsigned g_mxals[3][4];         // per-layer per-head global max(als), int-encoded
__device__ int   g_idx64;

// monotone float<->uint encoding for atomicMax on floats
__device__ __forceinline__ unsigned fenc(float f) {
    int b = __float_as_int(f);
    return (b >= 0) ? ((unsigned)b | 0x80000000u) : ~(unsigned)b;
}
__device__ __forceinline__ float fdec(unsigned u) {
    int b = (u & 0x80000000u) ? (int)(u & 0x7fffffffu) : ~(int)u;
    return __int_as_float(b);
}

// round-to-nearest tf32 conversion — REQUIRED: feeding raw fp32 bits to the
// tf32 MMA truncates (biased error, accumulates coherently over K).
__device__ __forceinline__ unsigned f2tf(float f) {
    unsigned u;
    asm("cvt.rna.tf32.f32 %0, %1;" : "=r"(u) : "f"(f));
    return u;
}

// ---------------- edge-index dtype detection (parallel vote) ----------------
__global__ void k_detect_idx(const void* ei_raw, int E) {
    __shared__ int ok;
    if (threadIdx.x == 0) ok = 1;
    __syncthreads();
    const long long* p = (const long long*)ei_raw;
    int nchk = 2 * E < 256 ? 2 * E : 256;
    if (threadIdx.x < nchk) {
        long long v = p[threadIdx.x];
        if (v < 0 || v >= NN) atomicAnd(&ok, 0);
    }
    __syncthreads();
    if (threadIdx.x == 0) g_idx64 = ok;
}

__device__ __forceinline__ void load_edge(const void* ei_raw, int E, int e, int idx64,
                                          int& s, int& d) {
    if (idx64) {
        const long long* p = (const long long*)ei_raw;
        s = (int)p[e];
        d = (int)p[E + e];
    } else {
        const int* p = (const int*)ei_raw;
        s = p[e];
        d = p[E + e];
    }
}

// ---------------- CSR construction ----------------
__global__ void k_zero_deg(int n) {
    int i = blockIdx.x * blockDim.x + threadIdx.x;
    if (i < n) g_deg[i] = 0;
}

__global__ void k_count_deg(const void* ei_raw, int E, int n) {
    int e = blockIdx.x * blockDim.x + threadIdx.x;
    int idx64 = g_idx64;
    if (e < E) {
        int s, d;
        load_edge(ei_raw, E, e, idx64, s, d);
        if (d >= 0 && d < n) atomicAdd(&g_deg[d], 1);
    }
}

__global__ void k_scan1(int n) {
    int t = threadIdx.x;
    int i = blockIdx.x * SCAN_B + t;
    int lane = t & 31, w = t >> 5;
    int v = (i < n) ? g_deg[i] : 0;
    int x = v;
#pragma unroll
    for (int o = 1; o < 32; o <<= 1) {
        int y = __shfl_up_sync(0xffffffffu, x, o);
        if (lane >= o) x += y;
    }
    __shared__ int ws[32];
    if (lane == 31) ws[w] = x;
    __syncthreads();
    if (w == 0) {
        int y = ws[lane];
#pragma unroll
        for (int o = 1; o < 32; o <<= 1) {
            int z = __shfl_up_sync(0xffffffffu, y, o);
            if (lane >= o) y += z;
        }
        ws[lane] = y;
    }
    __syncthreads();
    int incl = x + (w > 0 ? ws[w - 1] : 0);
    if (i < n) g_rowptr[i + 1] = incl;
    if (t == SCAN_B - 1) g_bsum[blockIdx.x] = incl;
}

__global__ void k_scan2() {
    int t = threadIdx.x;
    int lane = t & 31, w = t >> 5;
    if (t < 12) ((unsigned*)g_mxals)[t] = 0u;    // init per-layer max slots
    int v = (t < NBLK) ? g_bsum[t] : 0;
    int x = v;
#pragma unroll
    for (int o = 1; o < 32; o <<= 1) {
        int y = __shfl_up_sync(0xffffffffu, x, o);
        if (lane >= o) x += y;
    }
    __shared__ int ws[2];
    if (lane == 31) ws[w] = x;
    __syncthreads();
    int incl = x + (w > 0 ? ws[0] : 0);
    if (t < NBLK) g_boff[t] = incl - v;
}

__global__ void k_scan3(int n) {
    int i = blockIdx.x * blockDim.x + threadIdx.x;
    if (i < n) {
        int incl = g_rowptr[i + 1] + g_boff[i >> 10];
        g_rowptr[i + 1] = incl;
        g_cursor[i] = incl - g_deg[i];
        if (i == 0) g_rowptr[0] = 0;
    }
}

__global__ void k_scatter(const void* ei_raw, const float* __restrict__ ew, int E, int n) {
    int e = blockIdx.x * blockDim.x + threadIdx.x;
    int idx64 = g_idx64;
    if (e < E) {
        int s, d;
        load_edge(ei_raw, E, e, idx64, s, d);
        if (s >= 0 && s < n && d >= 0 && d < n) {
            int pos = atomicAdd(&g_cursor[d], 1);
            if (pos >= 0 && pos < E) {
                g_csr[pos] = make_int2(s, __float_as_int(ew[e]));
            }
        }
    }
}

// ---------------- TF32 tensor-core GEMM with register prefetch ----------------
// g_h[M,Nc] (fp32) = A[M,K] @ B[K,Nc].  BM=128, BN=64, BK=32, 8 warps, warp tile 32x32.
__global__ __launch_bounds__(256)
void k_gemm_tf32(const float* __restrict__ Aext, const float* __restrict__ B,
                 int M, int K, int Nc) {
    constexpr int BM = 128, BN = 64, BK = 32;
    constexpr int APAD = 36;
    constexpr int BPAD = 72;
    __shared__ __align__(16) unsigned As[BM][APAD];
    __shared__ __align__(16) unsigned Bs[BK][BPAD];

    const float* __restrict__ A = Aext ? Aext : g_act;
    float* __restrict__ C = g_h;

    int tid = threadIdx.x;
    int lane = tid & 31;
    int warp = tid >> 5;
    int wm = warp >> 1;
    int wn = warp & 1;
    int bm0 = blockIdx.y * BM;
    int bn0 = blockIdx.x * BN;

    float acc[2][4][4];
#pragma unroll
    for (int mt = 0; mt < 2; mt++)
#pragma unroll
        for (int nt = 0; nt < 4; nt++)
#pragma unroll
            for (int i = 0; i < 4; i++) acc[mt][nt][i] = 0.f;

    int arow = tid >> 1;
    int acol0 = (tid & 1) * 16;
    int brow = tid >> 3;
    int bcol0 = (tid & 7) * 4;
    int grow = bm0 + arow;

    float4 av[4];
    float4 bv[2];

    // prologue: load tile 0
    {
        const float* ap = A + (size_t)grow * K + acol0;
#pragma unroll
        for (int j = 0; j < 4; j++)
            av[j] = (grow < M) ? *(const float4*)(ap + j * 4)
                               : make_float4(0.f, 0.f, 0.f, 0.f);
        const float* bp = B + (size_t)brow * Nc + bn0;
#pragma unroll
        for (int it = 0; it < 2; it++)
            bv[it] = *(const float4*)(bp + bcol0 + it * 32);
    }
    int KT = K / BK;
    for (int kt = 0; kt < KT; kt++) {
        // store prefetched regs to smem WITH rna tf32 rounding
#pragma unroll
        for (int j = 0; j < 4; j++) {
            unsigned* dstp = &As[arow][acol0 + j * 4];
            dstp[0] = f2tf(av[j].x); dstp[1] = f2tf(av[j].y);
            dstp[2] = f2tf(av[j].z); dstp[3] = f2tf(av[j].w);
        }
#pragma unroll
        for (int it = 0; it < 2; it++) {
            unsigned* dstp = &Bs[brow][bcol0 + it * 32];
            dstp[0] = f2tf(bv[it].x); dstp[1] = f2tf(bv[it].y);
            dstp[2] = f2tf(bv[it].z); dstp[3] = f2tf(bv[it].w);
        }
        __syncthreads();

        // issue next tile's global loads (overlap with MMA below)
        if (kt + 1 < KT) {
            int k0 = (kt + 1) * BK;
            const float* ap = A + (size_t)grow * K + k0 + acol0;
#pragma unroll
            for (int j = 0; j < 4; j++)
                av[j] = (grow < M) ? *(const float4*)(ap + j * 4)
                                   : make_float4(0.f, 0.f, 0.f, 0.f);
            const float* bp = B + (size_t)(k0 + brow) * Nc + bn0;
#pragma unroll
            for (int it = 0; it < 2; it++)
                bv[it] = *(const float4*)(bp + bcol0 + it * 32);
        }

#pragma unroll
        for (int kc = 0; kc < BK; kc += 8) {
            unsigned afr[2][4];
            int r0 = wm * 32 + (lane >> 2);
            int cA = kc + (lane & 3);
#pragma unroll
            for (int mt = 0; mt < 2; mt++) {
                int rb = r0 + mt * 16;
                afr[mt][0] = As[rb][cA];
                afr[mt][1] = As[rb + 8][cA];
                afr[mt][2] = As[rb][cA + 4];
                afr[mt][3] = As[rb + 8][cA + 4];
            }
            unsigned bfr[4][2];
            int kB0 = kc + (lane & 3);
            int nB0 = wn * 32 + (lane >> 2);
#pragma unroll
            for (int nt = 0; nt < 4; nt++) {
                bfr[nt][0] = Bs[kB0][nB0 + nt * 8];
                bfr[nt][1] = Bs[kB0 + 4][nB0 + nt * 8];
            }
#pragma unroll
            for (int mt = 0; mt < 2; mt++)
#pragma unroll
                for (int nt = 0; nt < 4; nt++) {
                    asm volatile(
                        "mma.sync.aligned.m16n8k8.row.col.f32.tf32.tf32.f32 "
                        "{%0,%1,%2,%3}, {%4,%5,%6,%7}, {%8,%9}, {%0,%1,%2,%3};"
                        : "+f"(acc[mt][nt][0]), "+f"(acc[mt][nt][1]),
                          "+f"(acc[mt][nt][2]), "+f"(acc[mt][nt][3])
                        : "r"(afr[mt][0]), "r"(afr[mt][1]), "r"(afr[mt][2]), "r"(afr[mt][3]),
                          "r"(bfr[nt][0]), "r"(bfr[nt][1]));
                }
        }
        __syncthreads();
    }

    // epilogue: fp32 stores
#pragma unroll
    for (int mt = 0; mt < 2; mt++) {
        int r = bm0 + wm * 32 + mt * 16 + (lane >> 2);
#pragma unroll
        for (int nt = 0; nt < 4; nt++) {
            int c = bn0 + wn * 32 + nt * 8 + (lane & 3) * 2;
            if (r < M) {
                float2 v0 = make_float2(acc[mt][nt][0], acc[mt][nt][1]);
                *(float2*)(C + (size_t)r * Nc + c) = v0;
            }
            if (r + 8 < M) {
                float2 v1 = make_float2(acc[mt][nt][2], acc[mt][nt][3]);
                *(float2*)(C + (size_t)(r + 8) * Nc + c) = v1;
            }
        }
    }
}

// ---------------- attention dot products: g_als/g_ald [N,H] ----------------
template <int H, int C>
__global__ void k_dots(const float* __restrict__ a_src, const float* __restrict__ a_dst, int n) {
    constexpr int D = H * C;
    constexpr int CPL = D / 32;
    constexpr int G = 32 / H;
    int wid = threadIdx.x >> 5;
    int lane = threadIdx.x & 31;
    int node = blockIdx.x * 4 + wid;
    if (node >= n) return;
    int c0 = lane * CPL;
    float ss = 0.f, sd = 0.f;
    const float* hr = g_h + (size_t)node * D;
#pragma unroll
    for (int j = 0; j < CPL; j++) {
        float hv = hr[c0 + j];
        ss = fmaf(hv, a_src[c0 + j], ss);
        sd = fmaf(hv, a_dst[c0 + j], sd);
    }
#pragma unroll
    for (int o = G / 2; o > 0; o >>= 1) {
        ss += __shfl_down_sync(0xffffffffu, ss, o, G);
        sd += __shfl_down_sync(0xffffffffu, sd, o, G);
    }
    if ((lane % G) == 0) {
        int hd = lane / G;
        g_als[(size_t)node * H + hd] = ss;
        g_ald[(size_t)node * H + hd] = sd;
    }
}

// ---------------- global per-head max of als ----------------
template <int H, int LAYER>
__global__ void k_maxals(int n) {
    float mx[H];
#pragma unroll
    for (int hh = 0; hh < H; hh++) mx[hh] = -1e30f;
    for (int i = blockIdx.x * blockDim.x + threadIdx.x; i < n; i += gridDim.x * blockDim.x) {
        if (H == 4) {
            float4 v = *(const float4*)(g_als + (size_t)i * 4);
            mx[0] = fmaxf(mx[0], v.x); mx[1] = fmaxf(mx[1], v.y);
            mx[2] = fmaxf(mx[2], v.z); mx[3] = fmaxf(mx[3], v.w);
        } else {
            mx[0] = fmaxf(mx[0], g_als[i]);
        }
    }
#pragma unroll
    for (int hh = 0; hh < H; hh++)
#pragma unroll
        for (int o = 16; o > 0; o >>= 1)
            mx[hh] = fmaxf(mx[hh], __shfl_xor_sync(0xffffffffu, mx[hh], o));
    __shared__ float sm[8][H > 0 ? H : 1];
    int w = threadIdx.x >> 5, lane = threadIdx.x & 31;
    if (lane == 0)
#pragma unroll
        for (int hh = 0; hh < H; hh++) sm[w][hh] = mx[hh];
    __syncthreads();
    if (threadIdx.x == 0) {
#pragma unroll
        for (int hh = 0; hh < H; hh++) {
            float m = sm[0][hh];
            for (int ww = 1; ww < 8; ww++) m = fmaxf(m, sm[ww][hh]);
            atomicMax(&g_mxals[LAYER][hh], fenc(m));
        }
    }
}

// ---------------- fused segment softmax + weighted aggregate (single edge pass) ----------------
template <int H, int C, bool RELU, int LAYER>
__global__ void k_aggregate(const float* __restrict__ bias, float* __restrict__ outExt, int n) {
    constexpr int D = H * C;
    constexpr int CPL = D / 32;
    constexpr int G = 32 / H;
    float* __restrict__ out = outExt ? outExt : g_act;
    int wid = threadIdx.x >> 5;
    int lane = threadIdx.x & 31;
    int node = blockIdx.x * 4 + wid;
    if (node >= n) return;

    int s0 = g_rowptr[node];
    int s1 = g_rowptr[node + 1];

    int c0 = lane * CPL;
    int hd = lane / G;
    float myald = g_ald[(size_t)node * H + hd];
    // shift = leaky(global_max_als + ald) >= per-dst max of leaky(als+ald); exact softmax shift
    float Mh = fdec(g_mxals[LAYER][hd]);
    float mymx = Mh + myald;
    mymx = (mymx > 0.f) ? mymx : SLOPE * mymx;

    float acc[CPL];
#pragma unroll
    for (int j = 0; j < CPL; j++) acc[j] = 0.f;
    float esum = 0.f;
    for (int i = s0; i < s1; i++) {
        int2 p = g_csr[i];
        float w = __int_as_float(p.y);
        float l = g_als[(size_t)p.x * H + hd] + myald;
        l = (l > 0.f) ? l : SLOPE * l;
        float e = __expf(l - mymx) * w;
        esum += e;
        if (CPL == 4) {
            float4 v = *(const float4*)(g_h + (size_t)p.x * D + c0);
            acc[0] = fmaf(e, v.x, acc[0]);
            acc[1] = fmaf(e, v.y, acc[1]);
            acc[2] = fmaf(e, v.z, acc[2]);
            acc[3] = fmaf(e, v.w, acc[3]);
        } else {
            float2 v = *(const float2*)(g_h + (size_t)p.x * D + c0);
            acc[0] = fmaf(e, v.x, acc[0]);
            acc[1] = fmaf(e, v.y, acc[1]);
        }
    }
    float inv = 1.0f / (esum + 1e-16f);
#pragma unroll
    for (int j = 0; j < CPL; j++) {
        float v = fmaf(acc[j], inv, bias[c0 + j]);
        if (RELU) v = fmaxf(v, 0.f);
        out[(size_t)node * D + c0 + j] = v;
    }
}

// ---------------- host launch ----------------
extern "C" void kernel_launch(void* const* d_in, const int* in_sizes, int n_in,
                              void* d_out, int out_size) {
    const float* x   = (const float*)d_in[0];
    const void*  ei  = d_in[1];
    const float* ew  = (const float*)d_in[2];
    const float* W1  = (const float*)d_in[3];
    const float* aS1 = (const float*)d_in[4];
    const float* aD1 = (const float*)d_in[5];
    const float* b1  = (const float*)d_in[6];
    const float* W2  = (const float*)d_in[7];
    const float* aS2 = (const float*)d_in[8];
    const float* aD2 = (const float*)d_in[9];
    const float* b2  = (const float*)d_in[10];
    const float* W3  = (const float*)d_in[11];
    const float* aS3 = (const float*)d_in[12];
    const float* aD3 = (const float*)d_in[13];
    const float* b3  = (const float*)d_in[14];

    const int E = in_sizes[2];
    const int n = NN;

    // CSR build (reused by all 3 layers); scan2 also inits g_mxals
    k_detect_idx<<<1, 256>>>(ei, E);
    k_zero_deg<<<(n + 255) / 256, 256>>>(n);
    k_count_deg<<<(E + 255) / 256, 256>>>(ei, E, n);
    k_scan1<<<NBLK, SCAN_B>>>(n);
    k_scan2<<<1, 64>>>();
    k_scan3<<<(n + 255) / 256, 256>>>(n);
    k_scatter<<<(E + 255) / 256, 256>>>(ei, ew, E, n);

    const int nodeBlocks = (n + 3) / 4;
    dim3 gemmGrid2(D1 / 64, (n + 127) / 128);
    dim3 gemmGrid1(OUT_F / 64, (n + 127) / 128);

    // Layer 1: 256 -> 128, H=4, C=32, relu
    k_gemm_tf32<<<gemmGrid2, 256>>>(x, W1, n, IN_F, D1);
    k_dots<4, 32><<<nodeBlocks, 128>>>(aS1, aD1, n);
    k_maxals<4, 0><<<128, 256>>>(n);
    k_aggregate<4, 32, true, 0><<<nodeBlocks, 128>>>(b1, nullptr, n);

    // Layer 2: 128 -> 128, H=4, C=32, relu
    k_gemm_tf32<<<gemmGrid2, 256>>>(nullptr, W2, n, D1, D1);
    k_dots<4, 32><<<nodeBlocks, 128>>>(aS2, aD2, n);
    k_maxals<4, 1><<<128, 256>>>(n);
    k_aggregate<4, 32, true, 1><<<nodeBlocks, 128>>>(b2, nullptr, n);

    // Layer 3: 128 -> 64, H=1, C=64, no relu
    k_gemm_tf32<<<gemmGrid1, 256>>>(nullptr, W3, n, D1, OUT_F);
    k_dots<1, 64><<<nodeBlocks, 128>>>(aS3, aD3, n);
    k_maxals<1, 2><<<128, 256>>>(n);
    k_aggregate<1, 64, false, 2><<<nodeBlocks, 128>>>(b3, (float*)d_out, n);
}

// round 11
// speedup vs baseline: 1.0253x; 1.0253x over previous
#include <cuda_runtime.h>
#include <cuda_fp16.h>
#include <math.h>

// Problem constants (match reference)
#define NN 50000
#define NE 800000
#define IN_F 256
#define D1 128      // HEADS*HID
#define OUT_F 64
#define SLOPE 0.2f

#define SCAN_B 1024
#define NBLK ((NN + SCAN_B - 1) / SCAN_B)   // 49

// ---------------- device scratch (no allocations allowed) ----------------
__device__ __align__(16) __half g_h[(size_t)NN * D1];    // GEMM output, fp16 (gather path)
__device__ __align__(16) float  g_act[(size_t)NN * D1];  // post-aggregate activations, fp32
__device__ __align__(16) float  g_als[(size_t)NN * 4];
__device__ __align__(16) float  g_ald[(size_t)NN * 4];
__device__ int   g_rowptr[NN + 1];
__device__ int   g_deg[NN];
__device__ int   g_cursor[NN];
__device__ __align__(8) int2 g_csr[NE];    // (src, weight-bits) packed
__device__ int   g_bsum[NBLK];
__device__ int   g_boff[NBLK];
__device__ unsigned g_mxals[3][4];         // per-layer per-head global max(als), int-encoded
__device__ int   g_idx64;

// monotone float<->uint encoding for atomicMax on floats
__device__ __forceinline__ unsigned fenc(float f) {
    int b = __float_as_int(f);
    return (b >= 0) ? ((unsigned)b | 0x80000000u) : ~(unsigned)b;
}
__device__ __forceinline__ float fdec(unsigned u) {
    int b = (u & 0x80000000u) ? (int)(u & 0x7fffffffu) : ~(int)u;
    return __int_as_float(b);
}

// round-to-nearest tf32 conversion — REQUIRED (raw bits => biased truncation).
__device__ __forceinline__ unsigned f2tf(float f) {
    unsigned u;
    asm("cvt.rna.tf32.f32 %0, %1;" : "=r"(u) : "f"(f));
    return u;
}

// ---------------- edge-index dtype detection (parallel vote) ----------------
__global__ void k_detect_idx(const void* ei_raw, int E) {
    __shared__ int ok;
    if (threadIdx.x == 0) ok = 1;
    __syncthreads();
    const long long* p = (const long long*)ei_raw;
    int nchk = 2 * E < 256 ? 2 * E : 256;
    if (threadIdx.x < nchk) {
        long long v = p[threadIdx.x];
        if (v < 0 || v >= NN) atomicAnd(&ok, 0);
    }
    __syncthreads();
    if (threadIdx.x == 0) g_idx64 = ok;
}

__device__ __forceinline__ void load_edge(const void* ei_raw, int E, int e, int idx64,
                                          int& s, int& d) {
    if (idx64) {
        const long long* p = (const long long*)ei_raw;
        s = (int)p[e];
        d = (int)p[E + e];
    } else {
        const int* p = (const int*)ei_raw;
        s = p[e];
        d = p[E + e];
    }
}

// ---------------- CSR construction ----------------
__global__ void k_zero_deg(int n) {
    int i = blockIdx.x * blockDim.x + threadIdx.x;
    if (i < n) g_deg[i] = 0;
}

__global__ void k_count_deg(const void* ei_raw, int E, int n) {
    int e = blockIdx.x * blockDim.x + threadIdx.x;
    int idx64 = g_idx64;
    if (e < E) {
        int s, d;
        load_edge(ei_raw, E, e, idx64, s, d);
        if (d >= 0 && d < n) atomicAdd(&g_deg[d], 1);
    }
}

__global__ void k_scan1(int n) {
    int t = threadIdx.x;
    int i = blockIdx.x * SCAN_B + t;
    int lane = t & 31, w = t >> 5;
    int v = (i < n) ? g_deg[i] : 0;
    int x = v;
#pragma unroll
    for (int o = 1; o < 32; o <<= 1) {
        int y = __shfl_up_sync(0xffffffffu, x, o);
        if (lane >= o) x += y;
    }
    __shared__ int ws[32];
    if (lane == 31) ws[w] = x;
    __syncthreads();
    if (w == 0) {
        int y = ws[lane];
#pragma unroll
        for (int o = 1; o < 32; o <<= 1) {
            int z = __shfl_up_sync(0xffffffffu, y, o);
            if (lane >= o) y += z;
        }
        ws[lane] = y;
    }
    __syncthreads();
    int incl = x + (w > 0 ? ws[w - 1] : 0);
    if (i < n) g_rowptr[i + 1] = incl;
    if (t == SCAN_B - 1) g_bsum[blockIdx.x] = incl;
}

__global__ void k_scan2() {
    int t = threadIdx.x;
    int lane = t & 31, w = t >> 5;
    if (t < 12) ((unsigned*)g_mxals)[t] = 0u;    // init per-layer max slots
    int v = (t < NBLK) ? g_bsum[t] : 0;
    int x = v;
#pragma unroll
    for (int o = 1; o < 32; o <<= 1) {
        int y = __shfl_up_sync(0xffffffffu, x, o);
        if (lane >= o) x += y;
    }
    __shared__ int ws[2];
    if (lane == 31) ws[w] = x;
    __syncthreads();
    int incl = x + (w > 0 ? ws[0] : 0);
    if (t < NBLK) g_boff[t] = incl - v;
}

__global__ void k_scan3(int n) {
    int i = blockIdx.x * blockDim.x + threadIdx.x;
    if (i < n) {
        int incl = g_rowptr[i + 1] + g_boff[i >> 10];
        g_rowptr[i + 1] = incl;
        g_cursor[i] = incl - g_deg[i];
        if (i == 0) g_rowptr[0] = 0;
    }
}

__global__ void k_scatter(const void* ei_raw, const float* __restrict__ ew, int E, int n) {
    int e = blockIdx.x * blockDim.x + threadIdx.x;
    int idx64 = g_idx64;
    if (e < E) {
        int s, d;
        load_edge(ei_raw, E, e, idx64, s, d);
        if (s >= 0 && s < n && d >= 0 && d < n) {
            int pos = atomicAdd(&g_cursor[d], 1);
            if (pos >= 0 && pos < E) {
                g_csr[pos] = make_int2(s, __float_as_int(ew[e]));
            }
        }
    }
}

// ---------------- TF32 tensor-core GEMM (non-prefetch; proven fastest) ----------------
// g_h[M,Nc] (fp16) = A[M,K] @ B[K,Nc].  BM=128, BN=64, BK=32, 8 warps, warp tile 32x32.
__global__ __launch_bounds__(256)
void k_gemm_tf32(const float* __restrict__ Aext, const float* __restrict__ B,
                 int M, int K, int Nc) {
    constexpr int BM = 128, BN = 64, BK = 32;
    constexpr int APAD = 36;
    constexpr int BPAD = 72;
    __shared__ __align__(16) unsigned As[BM][APAD];
    __shared__ __align__(16) unsigned Bs[BK][BPAD];

    const float* __restrict__ A = Aext ? Aext : g_act;
    __half* __restrict__ C = g_h;

    int tid = threadIdx.x;
    int lane = tid & 31;
    int warp = tid >> 5;
    int wm = warp >> 1;
    int wn = warp & 1;
    int bm0 = blockIdx.y * BM;
    int bn0 = blockIdx.x * BN;

    float acc[2][4][4];
#pragma unroll
    for (int mt = 0; mt < 2; mt++)
#pragma unroll
        for (int nt = 0; nt < 4; nt++)
#pragma unroll
            for (int i = 0; i < 4; i++) acc[mt][nt][i] = 0.f;

    int arow = tid >> 1;
    int acol0 = (tid & 1) * 16;
    int brow = tid >> 3;
    int bcol0 = (tid & 7) * 4;
    int grow = bm0 + arow;

    for (int k0 = 0; k0 < K; k0 += BK) {
        const float* ap = A + (size_t)grow * K + k0 + acol0;
#pragma unroll
        for (int j = 0; j < 4; j++) {
            float4 v = (grow < M) ? *(const float4*)(ap + j * 4)
                                  : make_float4(0.f, 0.f, 0.f, 0.f);
            unsigned* dstp = &As[arow][acol0 + j * 4];
            dstp[0] = f2tf(v.x); dstp[1] = f2tf(v.y);
            dstp[2] = f2tf(v.z); dstp[3] = f2tf(v.w);
        }
        const float* bp = B + (size_t)(k0 + brow) * Nc + bn0;
#pragma unroll
        for (int it = 0; it < 2; it++) {
            float4 v = *(const float4*)(bp + bcol0 + it * 32);
            unsigned* dstp = &Bs[brow][bcol0 + it * 32];
            dstp[0] = f2tf(v.x); dstp[1] = f2tf(v.y);
            dstp[2] = f2tf(v.z); dstp[3] = f2tf(v.w);
        }
        __syncthreads();

#pragma unroll
        for (int kc = 0; kc < BK; kc += 8) {
            unsigned afr[2][4];
            int r0 = wm * 32 + (lane >> 2);
            int cA = kc + (lane & 3);
#pragma unroll
            for (int mt = 0; mt < 2; mt++) {
                int rb = r0 + mt * 16;
                afr[mt][0] = As[rb][cA];
                afr[mt][1] = As[rb + 8][cA];
                afr[mt][2] = As[rb][cA + 4];
                afr[mt][3] = As[rb + 8][cA + 4];
            }
            unsigned bfr[4][2];
            int kB0 = kc + (lane & 3);
            int nB0 = wn * 32 + (lane >> 2);
#pragma unroll
            for (int nt = 0; nt < 4; nt++) {
                bfr[nt][0] = Bs[kB0][nB0 + nt * 8];
                bfr[nt][1] = Bs[kB0 + 4][nB0 + nt * 8];
            }
#pragma unroll
            for (int mt = 0; mt < 2; mt++)
#pragma unroll
                for (int nt = 0; nt < 4; nt++) {
                    asm volatile(
                        "mma.sync.aligned.m16n8k8.row.col.f32.tf32.tf32.f32 "
                        "{%0,%1,%2,%3}, {%4,%5,%6,%7}, {%8,%9}, {%0,%1,%2,%3};"
                        : "+f"(acc[mt][nt][0]), "+f"(acc[mt][nt][1]),
                          "+f"(acc[mt][nt][2]), "+f"(acc[mt][nt][3])
                        : "r"(afr[mt][0]), "r"(afr[mt][1]), "r"(afr[mt][2]), "r"(afr[mt][3]),
                          "r"(bfr[nt][0]), "r"(bfr[nt][1]));
                }
        }
        __syncthreads();
    }

    // epilogue: fp32 acc -> fp16 stores
#pragma unroll
    for (int mt = 0; mt < 2; mt++) {
        int r = bm0 + wm * 32 + mt * 16 + (lane >> 2);
#pragma unroll
        for (int nt = 0; nt < 4; nt++) {
            int c = bn0 + wn * 32 + nt * 8 + (lane & 3) * 2;
            if (r < M) {
                __half2 v0 = __floats2half2_rn(acc[mt][nt][0], acc[mt][nt][1]);
                *(__half2*)(C + (size_t)r * Nc + c) = v0;
            }
            if (r + 8 < M) {
                __half2 v1 = __floats2half2_rn(acc[mt][nt][2], acc[mt][nt][3]);
                *(__half2*)(C + (size_t)(r + 8) * Nc + c) = v1;
            }
        }
    }
}

// ---------------- attention dot products: g_als/g_ald [N,H] (fp16 h) ----------------
template <int H, int C>
__global__ void k_dots(const float* __restrict__ a_src, const float* __restrict__ a_dst, int n) {
    constexpr int D = H * C;
    constexpr int CPL = D / 32;
    constexpr int G = 32 / H;
    int wid = threadIdx.x >> 5;
    int lane = threadIdx.x & 31;
    int node = blockIdx.x * 4 + wid;
    if (node >= n) return;
    int c0 = lane * CPL;
    float hv[CPL];
    const __half* hr = g_h + (size_t)node * D + c0;
    if (CPL == 4) {
        uint2 raw = *(const uint2*)hr;
        float2 f01 = __half22float2(*reinterpret_cast<__half2*>(&raw.x));
        float2 f23 = __half22float2(*reinterpret_cast<__half2*>(&raw.y));
        hv[0] = f01.x; hv[1] = f01.y; hv[2] = f23.x; hv[3] = f23.y;
    } else {
        unsigned raw = *(const unsigned*)hr;
        float2 f01 = __half22float2(*reinterpret_cast<__half2*>(&raw));
        hv[0] = f01.x; hv[1] = f01.y;
    }
    float ss = 0.f, sd = 0.f;
#pragma unroll
    for (int j = 0; j < CPL; j++) {
        ss = fmaf(hv[j], a_src[c0 + j], ss);
        sd = fmaf(hv[j], a_dst[c0 + j], sd);
    }
#pragma unroll
    for (int o = G / 2; o > 0; o >>= 1) {
        ss += __shfl_down_sync(0xffffffffu, ss, o, G);
        sd += __shfl_down_sync(0xffffffffu, sd, o, G);
    }
    if ((lane % G) == 0) {
        int hd = lane / G;
        g_als[(size_t)node * H + hd] = ss;
        g_ald[(size_t)node * H + hd] = sd;
    }
}

// ---------------- global per-head max of als ----------------
template <int H, int LAYER>
__global__ void k_maxals(int n) {
    float mx[H];
#pragma unroll
    for (int hh = 0; hh < H; hh++) mx[hh] = -1e30f;
    for (int i = blockIdx.x * blockDim.x + threadIdx.x; i < n; i += gridDim.x * blockDim.x) {
        if (H == 4) {
            float4 v = *(const float4*)(g_als + (size_t)i * 4);
            mx[0] = fmaxf(mx[0], v.x); mx[1] = fmaxf(mx[1], v.y);
            mx[2] = fmaxf(mx[2], v.z); mx[3] = fmaxf(mx[3], v.w);
        } else {
            mx[0] = fmaxf(mx[0], g_als[i]);
        }
    }
#pragma unroll
    for (int hh = 0; hh < H; hh++)
#pragma unroll
        for (int o = 16; o > 0; o >>= 1)
            mx[hh] = fmaxf(mx[hh], __shfl_xor_sync(0xffffffffu, mx[hh], o));
    __shared__ float sm[8][H > 0 ? H : 1];
    int w = threadIdx.x >> 5, lane = threadIdx.x & 31;
    if (lane == 0)
#pragma unroll
        for (int hh = 0; hh < H; hh++) sm[w][hh] = mx[hh];
    __syncthreads();
    if (threadIdx.x == 0) {
#pragma unroll
        for (int hh = 0; hh < H; hh++) {
            float m = sm[0][hh];
            for (int ww = 1; ww < 8; ww++) m = fmaxf(m, sm[ww][hh]);
            atomicMax(&g_mxals[LAYER][hh], fenc(m));
        }
    }
}

// ---------------- fused segment softmax + weighted aggregate (fp16 gather) ----------------
template <int H, int C, bool RELU, int LAYER>
__global__ void k_aggregate(const float* __restrict__ bias, float* __restrict__ outExt, int n) {
    constexpr int D = H * C;
    constexpr int CPL = D / 32;
    constexpr int G = 32 / H;
    float* __restrict__ out = outExt ? outExt : g_act;
    int wid = threadIdx.x >> 5;
    int lane = threadIdx.x & 31;
    int node = blockIdx.x * 4 + wid;
    if (node >= n) return;

    int s0 = g_rowptr[node];
    int s1 = g_rowptr[node + 1];

    int c0 = lane * CPL;
    int hd = lane / G;
    float myald = g_ald[(size_t)node * H + hd];
    // shift = leaky(global_max_als + ald) >= per-dst max of leaky(als+ald); exact softmax shift
    float Mh = fdec(g_mxals[LAYER][hd]);
    float mymx = Mh + myald;
    mymx = (mymx > 0.f) ? mymx : SLOPE * mymx;

    float acc[CPL];
#pragma unroll
    for (int j = 0; j < CPL; j++) acc[j] = 0.f;
    float esum = 0.f;
    for (int i = s0; i < s1; i++) {
        int2 p = g_csr[i];
        float w = __int_as_float(p.y);
        float l = g_als[(size_t)p.x * H + hd] + myald;
        l = (l > 0.f) ? l : SLOPE * l;
        float e = __expf(l - mymx) * w;
        esum += e;
        const __half* hp = g_h + (size_t)p.x * D + c0;
        if (CPL == 4) {
            uint2 raw = *(const uint2*)hp;
            float2 f01 = __half22float2(*reinterpret_cast<__half2*>(&raw.x));
            float2 f23 = __half22float2(*reinterpret_cast<__half2*>(&raw.y));
            acc[0] = fmaf(e, f01.x, acc[0]);
            acc[1] = fmaf(e, f01.y, acc[1]);
            acc[2] = fmaf(e, f23.x, acc[2]);
            acc[3] = fmaf(e, f23.y, acc[3]);
        } else {
            unsigned raw = *(const unsigned*)hp;
            float2 f01 = __half22float2(*reinterpret_cast<__half2*>(&raw));
            acc[0] = fmaf(e, f01.x, acc[0]);
            acc[1] = fmaf(e, f01.y, acc[1]);
        }
    }
    float inv = 1.0f / (esum + 1e-16f);
#pragma unroll
    for (int j = 0; j < CPL; j++) {
        float v = fmaf(acc[j], inv, bias[c0 + j]);
        if (RELU) v = fmaxf(v, 0.f);
        out[(size_t)node * D + c0 + j] = v;
    }
}

// ---------------- host launch ----------------
extern "C" void kernel_launch(void* const* d_in, const int* in_sizes, int n_in,
                              void* d_out, int out_size) {
    const float* x   = (const float*)d_in[0];
    const void*  ei  = d_in[1];
    const float* ew  = (const float*)d_in[2];
    const float* W1  = (const float*)d_in[3];
    const float* aS1 = (const float*)d_in[4];
    const float* aD1 = (const float*)d_in[5];
    const float* b1  = (const float*)d_in[6];
    const float* W2  = (const float*)d_in[7];
    const float* aS2 = (const float*)d_in[8];
    const float* aD2 = (const float*)d_in[9];
    const float* b2  = (const float*)d_in[10];
    const float* W3  = (const float*)d_in[11];
    const float* aS3 = (const float*)d_in[12];
    const float* aD3 = (const float*)d_in[13];
    const float* b3  = (const float*)d_in[14];

    const int E = in_sizes[2];
    const int n = NN;

    // CSR build (reused by all 3 layers); scan2 also inits g_mxals
    k_detect_idx<<<1, 256>>>(ei, E);
    k_zero_deg<<<(n + 255) / 256, 256>>>(n);
    k_count_deg<<<(E + 255) / 256, 256>>>(ei, E, n);
    k_scan1<<<NBLK, SCAN_B>>>(n);
    k_scan2<<<1, 64>>>();
    k_scan3<<<(n + 255) / 256, 256>>>(n);
    k_scatter<<<(E + 255) / 256, 256>>>(ei, ew, E, n);

    const int nodeBlocks = (n + 3) / 4;
    dim3 gemmGrid2(D1 / 64, (n + 127) / 128);
    dim3 gemmGrid1(OUT_F / 64, (n + 127) / 128);

    // Layer 1: 256 -> 128, H=4, C=32, relu
    k_gemm_tf32<<<gemmGrid2, 256>>>(x, W1, n, IN_F, D1);
    k_dots<4, 32><<<nodeBlocks, 128>>>(aS1, aD1, n);
    k_maxals<4, 0><<<128, 256>>>(n);
    k_aggregate<4, 32, true, 0><<<nodeBlocks, 128>>>(b1, nullptr, n);

    // Layer 2: 128 -> 128, H=4, C=32, relu
    k_gemm_tf32<<<gemmGrid2, 256>>>(nullptr, W2, n, D1, D1);
    k_dots<4, 32><<<nodeBlocks, 128>>>(aS2, aD2, n);
    k_maxals<4, 1><<<128, 256>>>(n);
    k_aggregate<4, 32, true, 1><<<nodeBlocks, 128>>>(b2, nullptr, n);

    // Layer 3: 128 -> 64, H=1, C=64, no relu
    k_gemm_tf32<<<gemmGrid1, 256>>>(nullptr, W3, n, D1, OUT_F);
    k_dots<1, 64><<<nodeBlocks, 128>>>(aS3, aD3, n);
    k_maxals<1, 2><<<128, 256>>>(n);
    k_aggregate<1, 64, false, 2><<<nodeBlocks, 128>>>(b3, (float*)d_out, n);
}

// round 12
// speedup vs baseline: 1.0428x; 1.0171x over previous
#include <cuda_runtime.h>
#include <cuda_fp16.h>
#include <math.h>

// Problem constants (match reference)
#define NN 50000
#define NE 800000
#define IN_F 256
#define D1 128      // HEADS*HID
#define OUT_F 64
#define SLOPE 0.2f

#define SCAN_B 1024
#define NBLK ((NN + SCAN_B - 1) / SCAN_B)   // 49

// ---------------- device scratch (no allocations allowed) ----------------
__device__ __align__(16) __half g_h[(size_t)NN * D1];    // GEMM output, fp16 (gather path)
__device__ __align__(16) float  g_act[(size_t)NN * D1];  // post-aggregate activations, fp32
__device__ __align__(16) float  g_als[(size_t)NN * 4];
__device__ __align__(16) float  g_ald[(size_t)NN * 4];
__device__ int   g_rowptr[NN + 1];
__device__ int   g_deg[NN];
__device__ int   g_cursor[NN];
__device__ __align__(8) int2 g_csr[NE];    // (src, weight-bits) packed
__device__ int   g_bsum[NBLK];
__device__ int   g_boff[NBLK];
__device__ unsigned g_mxals[3][4];         // per-layer per-head global max(als), int-encoded
__device__ int   g_idx64;

// monotone float<->uint encoding for atomicMax on floats (0u acts as -inf)
__device__ __forceinline__ unsigned fenc(float f) {
    int b = __float_as_int(f);
    return (b >= 0) ? ((unsigned)b | 0x80000000u) : ~(unsigned)b;
}
__device__ __forceinline__ float fdec(unsigned u) {
    int b = (u & 0x80000000u) ? (int)(u & 0x7fffffffu) : ~(int)u;
    return __int_as_float(b);
}

// round-to-nearest tf32 conversion — REQUIRED (raw bits => biased truncation).
__device__ __forceinline__ unsigned f2tf(float f) {
    unsigned u;
    asm("cvt.rna.tf32.f32 %0, %1;" : "=r"(u) : "f"(f));
    return u;
}

// ---------------- fused: zero deg + dtype detect (block 0) ----------------
__global__ void k_detect_zero(const void* ei_raw, int E, int n) {
    int i = blockIdx.x * blockDim.x + threadIdx.x;
    if (i < n) g_deg[i] = 0;
    if (blockIdx.x == 0) {
        __shared__ int ok;
        if (threadIdx.x == 0) ok = 1;
        __syncthreads();
        const long long* p = (const long long*)ei_raw;
        int nchk = 2 * E < 256 ? 2 * E : 256;
        if (threadIdx.x < nchk) {
            long long v = p[threadIdx.x];
            if (v < 0 || v >= NN) atomicAnd(&ok, 0);
        }
        __syncthreads();
        if (threadIdx.x == 0) g_idx64 = ok;
    }
}

__device__ __forceinline__ void load_edge(const void* ei_raw, int E, int e, int idx64,
                                          int& s, int& d) {
    if (idx64) {
        const long long* p = (const long long*)ei_raw;
        s = (int)p[e];
        d = (int)p[E + e];
    } else {
        const int* p = (const int*)ei_raw;
        s = p[e];
        d = p[E + e];
    }
}

// ---------------- CSR construction ----------------
__global__ void k_count_deg(const void* ei_raw, int E, int n) {
    int e = blockIdx.x * blockDim.x + threadIdx.x;
    int idx64 = g_idx64;
    if (e < E) {
        int s, d;
        load_edge(ei_raw, E, e, idx64, s, d);
        if (d >= 0 && d < n) atomicAdd(&g_deg[d], 1);
    }
}

__global__ void k_scan1(int n) {
    int t = threadIdx.x;
    int i = blockIdx.x * SCAN_B + t;
    int lane = t & 31, w = t >> 5;
    int v = (i < n) ? g_deg[i] : 0;
    int x = v;
#pragma unroll
    for (int o = 1; o < 32; o <<= 1) {
        int y = __shfl_up_sync(0xffffffffu, x, o);
        if (lane >= o) x += y;
    }
    __shared__ int ws[32];
    if (lane == 31) ws[w] = x;
    __syncthreads();
    if (w == 0) {
        int y = ws[lane];
#pragma unroll
        for (int o = 1; o < 32; o <<= 1) {
            int z = __shfl_up_sync(0xffffffffu, y, o);
            if (lane >= o) y += z;
        }
        ws[lane] = y;
    }
    __syncthreads();
    int incl = x + (w > 0 ? ws[w - 1] : 0);
    if (i < n) g_rowptr[i + 1] = incl;
    if (t == SCAN_B - 1) g_bsum[blockIdx.x] = incl;
}

__global__ void k_scan2() {
    int t = threadIdx.x;
    int lane = t & 31, w = t >> 5;
    if (t < 12) ((unsigned*)g_mxals)[t] = 0u;    // init per-layer max slots (before all dots)
    int v = (t < NBLK) ? g_bsum[t] : 0;
    int x = v;
#pragma unroll
    for (int o = 1; o < 32; o <<= 1) {
        int y = __shfl_up_sync(0xffffffffu, x, o);
        if (lane >= o) x += y;
    }
    __shared__ int ws[2];
    if (lane == 31) ws[w] = x;
    __syncthreads();
    int incl = x + (w > 0 ? ws[0] : 0);
    if (t < NBLK) g_boff[t] = incl - v;
}

__global__ void k_scan3(int n) {
    int i = blockIdx.x * blockDim.x + threadIdx.x;
    if (i < n) {
        int incl = g_rowptr[i + 1] + g_boff[i >> 10];
        g_rowptr[i + 1] = incl;
        g_cursor[i] = incl - g_deg[i];
        if (i == 0) g_rowptr[0] = 0;
    }
}

__global__ void k_scatter(const void* ei_raw, const float* __restrict__ ew, int E, int n) {
    int e = blockIdx.x * blockDim.x + threadIdx.x;
    int idx64 = g_idx64;
    if (e < E) {
        int s, d;
        load_edge(ei_raw, E, e, idx64, s, d);
        if (s >= 0 && s < n && d >= 0 && d < n) {
            int pos = atomicAdd(&g_cursor[d], 1);
            if (pos >= 0 && pos < E) {
                g_csr[pos] = make_int2(s, __float_as_int(ew[e]));
            }
        }
    }
}

// ---------------- TF32 tensor-core GEMM ----------------
// g_h[M,Nc] (fp16) = A[M,K] @ B[K,Nc].  BM=128, BN=64, BK=32, 8 warps, warp tile 32x32.
__global__ __launch_bounds__(256)
void k_gemm_tf32(const float* __restrict__ Aext, const float* __restrict__ B,
                 int M, int K, int Nc) {
    constexpr int BM = 128, BN = 64, BK = 32;
    constexpr int APAD = 36;
    constexpr int BPAD = 72;
    __shared__ __align__(16) unsigned As[BM][APAD];
    __shared__ __align__(16) unsigned Bs[BK][BPAD];

    const float* __restrict__ A = Aext ? Aext : g_act;
    __half* __restrict__ C = g_h;

    int tid = threadIdx.x;
    int lane = tid & 31;
    int warp = tid >> 5;
    int wm = warp >> 1;
    int wn = warp & 1;
    int bm0 = blockIdx.y * BM;
    int bn0 = blockIdx.x * BN;

    float acc[2][4][4];
#pragma unroll
    for (int mt = 0; mt < 2; mt++)
#pragma unroll
        for (int nt = 0; nt < 4; nt++)
#pragma unroll
            for (int i = 0; i < 4; i++) acc[mt][nt][i] = 0.f;

    int arow = tid >> 1;
    int acol0 = (tid & 1) * 16;
    int brow = tid >> 3;
    int bcol0 = (tid & 7) * 4;
    int grow = bm0 + arow;

    for (int k0 = 0; k0 < K; k0 += BK) {
        const float* ap = A + (size_t)grow * K + k0 + acol0;
#pragma unroll
        for (int j = 0; j < 4; j++) {
            float4 v = (grow < M) ? *(const float4*)(ap + j * 4)
                                  : make_float4(0.f, 0.f, 0.f, 0.f);
            unsigned* dstp = &As[arow][acol0 + j * 4];
            dstp[0] = f2tf(v.x); dstp[1] = f2tf(v.y);
            dstp[2] = f2tf(v.z); dstp[3] = f2tf(v.w);
        }
        const float* bp = B + (size_t)(k0 + brow) * Nc + bn0;
#pragma unroll
        for (int it = 0; it < 2; it++) {
            float4 v = *(const float4*)(bp + bcol0 + it * 32);
            unsigned* dstp = &Bs[brow][bcol0 + it * 32];
            dstp[0] = f2tf(v.x); dstp[1] = f2tf(v.y);
            dstp[2] = f2tf(v.z); dstp[3] = f2tf(v.w);
        }
        __syncthreads();

#pragma unroll
        for (int kc = 0; kc < BK; kc += 8) {
            unsigned afr[2][4];
            int r0 = wm * 32 + (lane >> 2);
            int cA = kc + (lane & 3);
#pragma unroll
            for (int mt = 0; mt < 2; mt++) {
                int rb = r0 + mt * 16;
                afr[mt][0] = As[rb][cA];
                afr[mt][1] = As[rb + 8][cA];
                afr[mt][2] = As[rb][cA + 4];
                afr[mt][3] = As[rb + 8][cA + 4];
            }
            unsigned bfr[4][2];
            int kB0 = kc + (lane & 3);
            int nB0 = wn * 32 + (lane >> 2);
#pragma unroll
            for (int nt = 0; nt < 4; nt++) {
                bfr[nt][0] = Bs[kB0][nB0 + nt * 8];
                bfr[nt][1] = Bs[kB0 + 4][nB0 + nt * 8];
            }
#pragma unroll
            for (int mt = 0; mt < 2; mt++)
#pragma unroll
                for (int nt = 0; nt < 4; nt++) {
                    asm volatile(
                        "mma.sync.aligned.m16n8k8.row.col.f32.tf32.tf32.f32 "
                        "{%0,%1,%2,%3}, {%4,%5,%6,%7}, {%8,%9}, {%0,%1,%2,%3};"
                        : "+f"(acc[mt][nt][0]), "+f"(acc[mt][nt][1]),
                          "+f"(acc[mt][nt][2]), "+f"(acc[mt][nt][3])
                        : "r"(afr[mt][0]), "r"(afr[mt][1]), "r"(afr[mt][2]), "r"(afr[mt][3]),
                          "r"(bfr[nt][0]), "r"(bfr[nt][1]));
                }
        }
        __syncthreads();
    }

    // epilogue: fp32 acc -> fp16 stores
#pragma unroll
    for (int mt = 0; mt < 2; mt++) {
        int r = bm0 + wm * 32 + mt * 16 + (lane >> 2);
#pragma unroll
        for (int nt = 0; nt < 4; nt++) {
            int c = bn0 + wn * 32 + nt * 8 + (lane & 3) * 2;
            if (r < M) {
                __half2 v0 = __floats2half2_rn(acc[mt][nt][0], acc[mt][nt][1]);
                *(__half2*)(C + (size_t)r * Nc + c) = v0;
            }
            if (r + 8 < M) {
                __half2 v1 = __floats2half2_rn(acc[mt][nt][2], acc[mt][nt][3]);
                *(__half2*)(C + (size_t)(r + 8) * Nc + c) = v1;
            }
        }
    }
}

// ---------------- dots + fused global max: g_als/g_ald [N,H], g_mxals[LAYER] ----------------
template <int H, int C, int LAYER>
__global__ void k_dots(const float* __restrict__ a_src, const float* __restrict__ a_dst, int n) {
    constexpr int D = H * C;
    constexpr int CPL = D / 32;
    constexpr int G = 32 / H;
    int wid = threadIdx.x >> 5;
    int lane = threadIdx.x & 31;
    int node = blockIdx.x * 4 + wid;
    bool valid = node < n;

    float ss = 0.f, sd = 0.f;
    int c0 = lane * CPL;
    if (valid) {
        float hv[CPL];
        const __half* hr = g_h + (size_t)node * D + c0;
        if (CPL == 4) {
            uint2 raw = *(const uint2*)hr;
            float2 f01 = __half22float2(*reinterpret_cast<__half2*>(&raw.x));
            float2 f23 = __half22float2(*reinterpret_cast<__half2*>(&raw.y));
            hv[0] = f01.x; hv[1] = f01.y; hv[2] = f23.x; hv[3] = f23.y;
        } else {
            unsigned raw = *(const unsigned*)hr;
            float2 f01 = __half22float2(*reinterpret_cast<__half2*>(&raw));
            hv[0] = f01.x; hv[1] = f01.y;
        }
#pragma unroll
        for (int j = 0; j < CPL; j++) {
            ss = fmaf(hv[j], a_src[c0 + j], ss);
            sd = fmaf(hv[j], a_dst[c0 + j], sd);
        }
    }
#pragma unroll
    for (int o = G / 2; o > 0; o >>= 1) {
        ss += __shfl_down_sync(0xffffffffu, ss, o, G);
        sd += __shfl_down_sync(0xffffffffu, sd, o, G);
    }
    __shared__ float smax[4][H];
    if ((lane % G) == 0) {
        int hd = lane / G;
        if (valid) {
            g_als[(size_t)node * H + hd] = ss;
            g_ald[(size_t)node * H + hd] = sd;
        }
        smax[wid][hd] = valid ? ss : -1e30f;
    }
    __syncthreads();
    if (threadIdx.x < H) {
        float m = smax[0][threadIdx.x];
#pragma unroll
        for (int ww = 1; ww < 4; ww++) m = fmaxf(m, smax[ww][threadIdx.x]);
        atomicMax(&g_mxals[LAYER][threadIdx.x], fenc(m));
    }
}

// ---------------- fused segment softmax + weighted aggregate (unrolled x4) ----------------
template <int H, int C, bool RELU, int LAYER>
__global__ void k_aggregate(const float* __restrict__ bias, float* __restrict__ outExt, int n) {
    constexpr int D = H * C;
    constexpr int CPL = D / 32;
    constexpr int G = 32 / H;
    float* __restrict__ out = outExt ? outExt : g_act;
    int wid = threadIdx.x >> 5;
    int lane = threadIdx.x & 31;
    int node = blockIdx.x * 4 + wid;
    if (node >= n) return;

    int s0 = g_rowptr[node];
    int s1 = g_rowptr[node + 1];

    int c0 = lane * CPL;
    int hd = lane / G;
    float myald = g_ald[(size_t)node * H + hd];
    float Mh = fdec(g_mxals[LAYER][hd]);
    float mymx = Mh + myald;
    mymx = (mymx > 0.f) ? mymx : SLOPE * mymx;

    float acc[CPL];
#pragma unroll
    for (int j = 0; j < CPL; j++) acc[j] = 0.f;
    float esum = 0.f;

    int i = s0;
    for (; i + 4 <= s1; i += 4) {
        // batch loads: csr, als, h — 4-wide MLP
        int2 p0 = g_csr[i + 0];
        int2 p1 = g_csr[i + 1];
        int2 p2 = g_csr[i + 2];
        int2 p3 = g_csr[i + 3];
        float a0 = g_als[(size_t)p0.x * H + hd];
        float a1 = g_als[(size_t)p1.x * H + hd];
        float a2 = g_als[(size_t)p2.x * H + hd];
        float a3 = g_als[(size_t)p3.x * H + hd];
        if (CPL == 4) {
            uint2 r0 = *(const uint2*)(g_h + (size_t)p0.x * D + c0);
            uint2 r1 = *(const uint2*)(g_h + (size_t)p1.x * D + c0);
            uint2 r2 = *(const uint2*)(g_h + (size_t)p2.x * D + c0);
            uint2 r3 = *(const uint2*)(g_h + (size_t)p3.x * D + c0);
            float l0 = a0 + myald; l0 = (l0 > 0.f) ? l0 : SLOPE * l0;
            float l1 = a1 + myald; l1 = (l1 > 0.f) ? l1 : SLOPE * l1;
            float l2 = a2 + myald; l2 = (l2 > 0.f) ? l2 : SLOPE * l2;
            float l3 = a3 + myald; l3 = (l3 > 0.f) ? l3 : SLOPE * l3;
            float e0 = __expf(l0 - mymx) * __int_as_float(p0.y);
            float e1 = __expf(l1 - mymx) * __int_as_float(p1.y);
            float e2 = __expf(l2 - mymx) * __int_as_float(p2.y);
            float e3 = __expf(l3 - mymx) * __int_as_float(p3.y);
            esum += (e0 + e1) + (e2 + e3);
            float2 f;
            f = __half22float2(*reinterpret_cast<__half2*>(&r0.x));
            acc[0] = fmaf(e0, f.x, acc[0]); acc[1] = fmaf(e0, f.y, acc[1]);
            f = __half22float2(*reinterpret_cast<__half2*>(&r0.y));
            acc[2] = fmaf(e0, f.x, acc[2]); acc[3] = fmaf(e0, f.y, acc[3]);
            f = __half22float2(*reinterpret_cast<__half2*>(&r1.x));
            acc[0] = fmaf(e1, f.x, acc[0]); acc[1] = fmaf(e1, f.y, acc[1]);
            f = __half22float2(*reinterpret_cast<__half2*>(&r1.y));
            acc[2] = fmaf(e1, f.x, acc[2]); acc[3] = fmaf(e1, f.y, acc[3]);
            f = __half22float2(*reinterpret_cast<__half2*>(&r2.x));
            acc[0] = fmaf(e2, f.x, acc[0]); acc[1] = fmaf(e2, f.y, acc[1]);
            f = __half22float2(*reinterpret_cast<__half2*>(&r2.y));
            acc[2] = fmaf(e2, f.x, acc[2]); acc[3] = fmaf(e2, f.y, acc[3]);
            f = __half22float2(*reinterpret_cast<__half2*>(&r3.x));
            acc[0] = fmaf(e3, f.x, acc[0]); acc[1] = fmaf(e3, f.y, acc[1]);
            f = __half22float2(*reinterpret_cast<__half2*>(&r3.y));
            acc[2] = fmaf(e3, f.x, acc[2]); acc[3] = fmaf(e3, f.y, acc[3]);
        } else {
            unsigned r0 = *(const unsigned*)(g_h + (size_t)p0.x * D + c0);
            unsigned r1 = *(const unsigned*)(g_h + (size_t)p1.x * D + c0);
            unsigned r2 = *(const unsigned*)(g_h + (size_t)p2.x * D + c0);
            unsigned r3 = *(const unsigned*)(g_h + (size_t)p3.x * D + c0);
            float l0 = a0 + myald; l0 = (l0 > 0.f) ? l0 : SLOPE * l0;
            float l1 = a1 + myald; l1 = (l1 > 0.f) ? l1 : SLOPE * l1;
            float l2 = a2 + myald; l2 = (l2 > 0.f) ? l2 : SLOPE * l2;
            float l3 = a3 + myald; l3 = (l3 > 0.f) ? l3 : SLOPE * l3;
            float e0 = __expf(l0 - mymx) * __int_as_float(p0.y);
            float e1 = __expf(l1 - mymx) * __int_as_float(p1.y);
            float e2 = __expf(l2 - mymx) * __int_as_float(p2.y);
            float e3 = __expf(l3 - mymx) * __int_as_float(p3.y);
            esum += (e0 + e1) + (e2 + e3);
            float2 f;
            f = __half22float2(*reinterpret_cast<__half2*>(&r0));
            acc[0] = fmaf(e0, f.x, acc[0]); acc[1] = fmaf(e0, f.y, acc[1]);
            f = __half22float2(*reinterpret_cast<__half2*>(&r1));
            acc[0] = fmaf(e1, f.x, acc[0]); acc[1] = fmaf(e1, f.y, acc[1]);
            f = __half22float2(*reinterpret_cast<__half2*>(&r2));
            acc[0] = fmaf(e2, f.x, acc[0]); acc[1] = fmaf(e2, f.y, acc[1]);
            f = __half22float2(*reinterpret_cast<__half2*>(&r3));
            acc[0] = fmaf(e3, f.x, acc[0]); acc[1] = fmaf(e3, f.y, acc[1]);
        }
    }
    for (; i < s1; i++) {
        int2 p = g_csr[i];
        float l = g_als[(size_t)p.x * H + hd] + myald;
        l = (l > 0.f) ? l : SLOPE * l;
        float e = __expf(l - mymx) * __int_as_float(p.y);
        esum += e;
        const __half* hp = g_h + (size_t)p.x * D + c0;
        if (CPL == 4) {
            uint2 raw = *(const uint2*)hp;
            float2 f01 = __half22float2(*reinterpret_cast<__half2*>(&raw.x));
            float2 f23 = __half22float2(*reinterpret_cast<__half2*>(&raw.y));
            acc[0] = fmaf(e, f01.x, acc[0]);
            acc[1] = fmaf(e, f01.y, acc[1]);
            acc[2] = fmaf(e, f23.x, acc[2]);
            acc[3] = fmaf(e, f23.y, acc[3]);
        } else {
            unsigned raw = *(const unsigned*)hp;
            float2 f01 = __half22float2(*reinterpret_cast<__half2*>(&raw));
            acc[0] = fmaf(e, f01.x, acc[0]);
            acc[1] = fmaf(e, f01.y, acc[1]);
        }
    }
    float inv = 1.0f / (esum + 1e-16f);
#pragma unroll
    for (int j = 0; j < CPL; j++) {
        float v = fmaf(acc[j], inv, bias[c0 + j]);
        if (RELU) v = fmaxf(v, 0.f);
        out[(size_t)node * D + c0 + j] = v;
    }
}

// ---------------- host launch ----------------
extern "C" void kernel_launch(void* const* d_in, const int* in_sizes, int n_in,
                              void* d_out, int out_size) {
    const float* x   = (const float*)d_in[0];
    const void*  ei  = d_in[1];
    const float* ew  = (const float*)d_in[2];
    const float* W1  = (const float*)d_in[3];
    const float* aS1 = (const float*)d_in[4];
    const float* aD1 = (const float*)d_in[5];
    const float* b1  = (const float*)d_in[6];
    const float* W2  = (const float*)d_in[7];
    const float* aS2 = (const float*)d_in[8];
    const float* aD2 = (const float*)d_in[9];
    const float* b2  = (const float*)d_in[10];
    const float* W3  = (const float*)d_in[11];
    const float* aS3 = (const float*)d_in[12];
    const float* aD3 = (const float*)d_in[13];
    const float* b3  = (const float*)d_in[14];

    const int E = in_sizes[2];
    const int n = NN;

    const int nodeBlocks = (n + 3) / 4;
    dim3 gemmGrid2(D1 / 64, (n + 127) / 128);
    dim3 gemmGrid1(OUT_F / 64, (n + 127) / 128);

    // CSR build + layer-1 GEMM interleaved; GEMM placed 4th so ncu profiles it.
    k_detect_zero<<<(n + 255) / 256, 256>>>(ei, E, n);            // 1
    k_count_deg<<<(E + 255) / 256, 256>>>(ei, E, n);              // 2
    k_scan1<<<NBLK, SCAN_B>>>(n);                                  // 3
    k_gemm_tf32<<<gemmGrid2, 256>>>(x, W1, n, IN_F, D1);          // 4  <- profiled
    k_scan2<<<1, 64>>>();                                          // 5
    k_scan3<<<(n + 255) / 256, 256>>>(n);                          // 6
    k_scatter<<<(E + 255) / 256, 256>>>(ei, ew, E, n);             // 7

    // Layer 1: 256 -> 128, H=4, C=32, relu
    k_dots<4, 32, 0><<<nodeBlocks, 128>>>(aS1, aD1, n);
    k_aggregate<4, 32, true, 0><<<nodeBlocks, 128>>>(b1, nullptr, n);

    // Layer 2: 128 -> 128, H=4, C=32, relu
    k_gemm_tf32<<<gemmGrid2, 256>>>(nullptr, W2, n, D1, D1);
    k_dots<4, 32, 1><<<nodeBlocks, 128>>>(aS2, aD2, n);
    k_aggregate<4, 32, true, 1><<<nodeBlocks, 128>>>(b2, nullptr, n);

    // Layer 3: 128 -> 64, H=1, C=64, no relu
    k_gemm_tf32<<<gemmGrid1, 256>>>(nullptr, W3, n, D1, OUT_F);
    k_dots<1, 64, 2><<<nodeBlocks, 128>>>(aS3, aD3, n);
    k_aggregate<1, 64, false, 2><<<nodeBlocks, 128>>>(b3, (float*)d_out, n);
}